// round 8
// baseline (speedup 1.0000x reference)
#include <cuda_runtime.h>
#include <cuda_bf16.h>
#include <math.h>

#define NN 50000
#define EE 600000
#define HH 128
#define GG 256
#define LL 4

// ---------------- scratch (static device allocations, legal) ----------------
__device__ float g_h[(size_t)NN * HH];
__device__ float g_A[(size_t)NN * HH];
__device__ float g_B[(size_t)NN * HH];
__device__ float g_S[(size_t)NN * HH];
__device__ float g_R[(size_t)NN * HH];
__device__ float g_agg[(size_t)NN * HH];
__device__ float g_pool[GG * HH];
__device__ int   g_send[EE];
__device__ int   g_rec[EE];
__device__ int   g_batch[NN];
__device__ int   g_start[GG + 1];
__device__ int   g_flag_e;
__device__ int   g_flag_b;

// ---------------- dtype detection (int64 vs int32) ----------------
__global__ void detect_kernel(const int* ei_words, const int* ba_words) {
    if (blockIdx.x != 0 || threadIdx.x != 0) return;
    int zeros = 0;
    for (int i = 0; i < 1024; i++) zeros += (ei_words[2 * i + 1] == 0);
    g_flag_e = (zeros > 512);
    int zb = 0;
    for (int i = 0; i < 1024; i++) {
        int w = NN / 2 + 2 * i + 1;   // valid word index for both widths
        zb += (ba_words[w] == 0);
    }
    g_flag_b = (zb > 512);
}

__global__ void convert_edges(const void* ei) {
    int i = blockIdx.x * blockDim.x + threadIdx.x;
    if (i >= EE) return;
    if (g_flag_e) {
        const long long* p = (const long long*)ei;
        g_send[i] = (int)p[i];
        g_rec[i]  = (int)p[EE + i];
    } else {
        const int* p = (const int*)ei;
        g_send[i] = p[i];
        g_rec[i]  = p[EE + i];
    }
}

__global__ void convert_batch(const void* ba) {
    int i = blockIdx.x * blockDim.x + threadIdx.x;
    if (i >= NN) return;
    if (g_flag_b) g_batch[i] = (int)((const long long*)ba)[i];
    else          g_batch[i] = ((const int*)ba)[i];
}

// ---------------- graph boundaries from sorted batch ----------------
__global__ void bounds_kernel() {
    int i = blockIdx.x * blockDim.x + threadIdx.x;
    if (i >= NN) return;
    int b = g_batch[i];
    if (i == 0) {
        for (int g = 0; g <= b; g++) g_start[g] = 0;
    } else {
        int pb = g_batch[i - 1];
        for (int g = pb + 1; g <= b; g++) g_start[g] = i;
    }
    if (i == NN - 1) {
        for (int g = b + 1; g <= GG; g++) g_start[g] = NN;
    }
}

// ---------------- embed: block per node, thread per output feature ----------------
__global__ __launch_bounds__(HH) void embed_kernel(const float* __restrict__ h_in,
                                                   const float* __restrict__ W,
                                                   const float* __restrict__ b) {
    int n = blockIdx.x;
    int j = threadIdx.x;
    __shared__ float hs[HH];
    hs[j] = h_in[(size_t)n * HH + j];
    __syncthreads();
    float acc = b[j];
    for (int k = 0; k < HH; k++) acc += hs[k] * W[k * HH + j];
    g_h[(size_t)n * HH + j] = acc;
}

// ---------------- per-layer linear: A,B,S,R for one node per block ----------------
// A = h @ Wg[l][0:128]   + bg[l]
// B = h @ Wg[l][128:256]
// S = h @ Ws[l]          + bs[l]
// R = h @ Wr[l]          + br[l]
__global__ __launch_bounds__(512) void absr_kernel(const float* __restrict__ Wg,
                                                   const float* __restrict__ bg,
                                                   const float* __restrict__ Ws,
                                                   const float* __restrict__ bs,
                                                   const float* __restrict__ Wr,
                                                   const float* __restrict__ br,
                                                   int l) {
    int n = blockIdx.x;
    int t = threadIdx.x;
    int which = t >> 7;      // 0=A 1=B 2=S 3=R
    int j = t & 127;
    __shared__ float hs[HH];
    if (t < HH) hs[t] = g_h[(size_t)n * HH + t];
    __syncthreads();

    const float* W;
    float bias;
    if (which == 0)      { W = Wg + ((size_t)l * 2 * HH) * HH;        bias = bg[l * HH + j]; }
    else if (which == 1) { W = Wg + ((size_t)l * 2 * HH + HH) * HH;   bias = 0.f; }
    else if (which == 2) { W = Ws + ((size_t)l * HH) * HH;            bias = bs[l * HH + j]; }
    else                 { W = Wr + ((size_t)l * HH) * HH;            bias = br[l * HH + j]; }

    float acc = bias;
    for (int k = 0; k < HH; k++) acc += hs[k] * W[k * HH + j];

    size_t idx = (size_t)n * HH + j;
    if (which == 0)      g_A[idx] = acc;
    else if (which == 1) g_B[idx] = acc;
    else if (which == 2) g_S[idx] = acc;
    else                 g_R[idx] = acc;
}

// ---------------- zero fill ----------------
__global__ void zero_agg_kernel() {
    size_t i = (size_t)blockIdx.x * blockDim.x + threadIdx.x;
    if (i < (size_t)NN * HH) g_agg[i] = 0.f;
}

// ---------------- edge: thread per (edge, feature) ----------------
__global__ __launch_bounds__(256) void edge_kernel() {
    size_t gtid = (size_t)blockIdx.x * blockDim.x + threadIdx.x;
    if (gtid >= (size_t)EE * HH) return;
    int e = (int)(gtid >> 7);
    int j = (int)(gtid & 127);
    int r = g_rec[e], s = g_send[e];
    float gate_in = g_A[(size_t)r * HH + j] + g_B[(size_t)s * HH + j];
    float eta = 1.0f / (1.0f + expf(-gate_in));
    float msg = eta * g_S[(size_t)s * HH + j];
    atomicAdd(&g_agg[(size_t)r * HH + j], msg);
}

// ---------------- node update: h += relu(R + agg) ----------------
__global__ void update_kernel() {
    size_t i = (size_t)blockIdx.x * blockDim.x + threadIdx.x;
    if (i >= (size_t)NN * HH) return;
    float v = g_R[i] + g_agg[i];
    g_h[i] += fmaxf(v, 0.f);
}

// ---------------- pool: block per graph, thread per feature ----------------
__global__ __launch_bounds__(HH) void pool_kernel() {
    int g = blockIdx.x;
    int j = threadIdx.x;
    int n0 = g_start[g], n1 = g_start[g + 1];
    float s = 0.f;
    for (int n = n0; n < n1; n++) s += g_h[(size_t)n * HH + j];
    g_pool[g * HH + j] = s;
}

// ---------------- readout MLP: block per graph ----------------
__global__ __launch_bounds__(64) void mlp_kernel(const float* __restrict__ W1,
                                                 const float* __restrict__ b1,
                                                 const float* __restrict__ W2,
                                                 const float* __restrict__ b2,
                                                 float* __restrict__ out) {
    int g = blockIdx.x;
    int j = threadIdx.x;            // 0..63
    __shared__ float hp[HH];
    __shared__ float red[64];
    hp[j] = g_pool[g * HH + j];
    hp[64 + j] = g_pool[g * HH + 64 + j];
    __syncthreads();
    float acc = b1[j];
    for (int k = 0; k < HH; k++) acc += hp[k] * W1[k * 64 + j];
    red[j] = fmaxf(acc, 0.f) * W2[j];
    for (int off = 32; off > 0; off >>= 1) {
        __syncthreads();
        if (j < off) red[j] += red[j + off];
    }
    __syncthreads();
    if (j == 0) out[g] = red[0] + b2[0];
}

// ---------------- launch ----------------
extern "C" void kernel_launch(void* const* d_in, const int* in_sizes, int n_in,
                              void* d_out, int out_size)
{
    // Size-based resolution (coincides with insertion order; robust to any
    // stable ordering that preserves relative order within equal sizes).
    int used[64];
    for (int i = 0; i < 64; i++) used[i] = 0;
    auto find = [&](long long s1, long long s2) -> const void* {
        for (int i = 0; i < n_in; i++) {
            if (used[i]) continue;
            if ((long long)in_sizes[i] == s1 ||
                (s2 && (long long)in_sizes[i] == s2)) {
                used[i] = 1;
                return d_in[i];
            }
        }
        return d_in[0];
    };

    const float* h_in    = (const float*)find(6400000, 0);
    const void*  ei      = find(1200000, 2400000);
    const void*  ba      = find(50000, 100000);
    const float* Wg      = (const float*)find(131072, 0);
    const float* Ws      = (const float*)find(65536, 0);   // first 65536 (Ws before Wr)
    const float* Wr      = (const float*)find(65536, 0);
    const float* W_embed = (const float*)find(16384, 0);
    const float* W1      = (const float*)find(8192, 0);
    const float* bg      = (const float*)find(512, 0);     // bg, bs, br in order
    const float* bs      = (const float*)find(512, 0);
    const float* br      = (const float*)find(512, 0);
    const float* b_embed = (const float*)find(128, 0);
    const float* b1      = (const float*)find(64, 0);      // b1 before W2
    const float* W2      = (const float*)find(64, 0);
    const float* b2      = (const float*)find(1, 0);
    float* out = (float*)d_out;

    detect_kernel<<<1, 1>>>((const int*)ei, (const int*)ba);
    convert_edges<<<(EE + 255) / 256, 256>>>(ei);
    convert_batch<<<(NN + 255) / 256, 256>>>(ba);
    bounds_kernel<<<(NN + 255) / 256, 256>>>();

    embed_kernel<<<NN, HH>>>(h_in, W_embed, b_embed);

    const size_t edge_work = (size_t)EE * HH;
    const size_t node_work = (size_t)NN * HH;

    for (int l = 0; l < LL; l++) {
        absr_kernel<<<NN, 512>>>(Wg, bg, Ws, bs, Wr, br, l);
        zero_agg_kernel<<<(int)((node_work + 255) / 256), 256>>>();
        edge_kernel<<<(int)((edge_work + 255) / 256), 256>>>();
        update_kernel<<<(int)((node_work + 255) / 256), 256>>>();
    }

    pool_kernel<<<GG, HH>>>();
    mlp_kernel<<<GG, 64>>>(W1, b1, W2, b2, out);
}

// round 11
// speedup vs baseline: 2.5406x; 2.5406x over previous
#include <cuda_runtime.h>
#include <cuda_bf16.h>
#include <math.h>

#define NN 50000
#define EE 600000
#define HH 128
#define GG 256
#define LL 4

// ---------------- scratch (static device allocations, legal) ----------------
__device__ float g_h[(size_t)NN * HH];
__device__ float g_A[(size_t)NN * HH];
__device__ float g_B[(size_t)NN * HH];
__device__ float g_S[(size_t)NN * HH];
__device__ float g_R[(size_t)NN * HH];
__device__ float g_agg[(size_t)NN * HH];
__device__ float g_pool[GG * HH];
__device__ int   g_send[EE];
__device__ int   g_rec[EE];
__device__ int   g_batch[NN];
__device__ int   g_start[GG + 1];
__device__ int   g_flag_e;
__device__ int   g_flag_b;

// ---------------- dtype detection (int64 vs int32) ----------------
__global__ void detect_kernel(const int* ei_words, const int* ba_words) {
    if (blockIdx.x != 0 || threadIdx.x != 0) return;
    int zeros = 0;
    for (int i = 0; i < 1024; i++) zeros += (ei_words[2 * i + 1] == 0);
    g_flag_e = (zeros > 512);
    int zb = 0;
    for (int i = 0; i < 1024; i++) {
        int w = NN / 2 + 2 * i + 1;
        zb += (ba_words[w] == 0);
    }
    g_flag_b = (zb > 512);
}

__global__ void convert_edges(const void* ei) {
    int i = blockIdx.x * blockDim.x + threadIdx.x;
    if (i >= EE) return;
    if (g_flag_e) {
        const long long* p = (const long long*)ei;
        g_send[i] = (int)p[i];
        g_rec[i]  = (int)p[EE + i];
    } else {
        const int* p = (const int*)ei;
        g_send[i] = p[i];
        g_rec[i]  = p[EE + i];
    }
}

__global__ void convert_batch(const void* ba) {
    int i = blockIdx.x * blockDim.x + threadIdx.x;
    if (i >= NN) return;
    if (g_flag_b) g_batch[i] = (int)((const long long*)ba)[i];
    else          g_batch[i] = ((const int*)ba)[i];
}

// ---------------- graph boundaries from sorted batch ----------------
__global__ void bounds_kernel() {
    int i = blockIdx.x * blockDim.x + threadIdx.x;
    if (i >= NN) return;
    int b = g_batch[i];
    if (i == 0) {
        for (int g = 0; g <= b; g++) g_start[g] = 0;
    } else {
        int pb = g_batch[i - 1];
        for (int g = pb + 1; g <= b; g++) g_start[g] = i;
    }
    if (i == NN - 1) {
        for (int g = b + 1; g <= GG; g++) g_start[g] = NN;
    }
}

// ---------------- tiled SGEMM: C[M,128] = A[M,128] @ W[128,128] (+bias) ----
// Block tile: 64 rows x 128 cols. 256 threads, each computes 4x8 outputs.
__global__ __launch_bounds__(256) void gemm128(const float* __restrict__ A,
                                               const float* __restrict__ W,
                                               const float* __restrict__ bias,
                                               float* __restrict__ C, int M)
{
    __shared__ float As[8][64];    // [k][row], transposed for broadcast reads
    __shared__ float Bs[8][128];   // [k][col]
    const int t = threadIdx.x;
    const int rowBase = blockIdx.x * 64;
    const int ty = t >> 4;          // 0..15 -> rows ty*4 .. ty*4+3
    const int tx = t & 15;          // 0..15 -> cols tx*8 .. tx*8+7

    // A-tile load mapping: 64 rows x 8 k = 512 floats; thread loads float2.
    const int aRow = t >> 2;            // 0..63
    const int aK2  = (t & 3) * 2;       // 0,2,4,6
    // B-tile load mapping: 8 rows x 128 cols = 1024 floats; thread loads float4.
    const int bRow  = t >> 5;           // 0..7
    const int bCol4 = (t & 31) * 4;     // 0..124

    float acc[4][8] = {};

    for (int kt = 0; kt < HH; kt += 8) {
        // stage A (guarded rows -> zero)
        float2 av = make_float2(0.f, 0.f);
        int gm = rowBase + aRow;
        if (gm < M) av = *(const float2*)(A + (size_t)gm * HH + kt + aK2);
        As[aK2 + 0][aRow] = av.x;
        As[aK2 + 1][aRow] = av.y;
        // stage W
        float4 wv = *(const float4*)(W + (size_t)(kt + bRow) * HH + bCol4);
        *(float4*)&Bs[bRow][bCol4] = wv;
        __syncthreads();

#pragma unroll
        for (int k = 0; k < 8; k++) {
            float ra[4], rb[8];
#pragma unroll
            for (int i = 0; i < 4; i++) ra[i] = As[k][ty * 4 + i];
#pragma unroll
            for (int j = 0; j < 8; j++) rb[j] = Bs[k][tx * 8 + j];
#pragma unroll
            for (int i = 0; i < 4; i++)
#pragma unroll
                for (int j = 0; j < 8; j++)
                    acc[i][j] += ra[i] * rb[j];
        }
        __syncthreads();
    }

#pragma unroll
    for (int i = 0; i < 4; i++) {
        int gm = rowBase + ty * 4 + i;
        if (gm >= M) continue;
        float* dst = C + (size_t)gm * HH + tx * 8;
        if (bias) {
#pragma unroll
            for (int j = 0; j < 8; j++) dst[j] = acc[i][j] + bias[tx * 8 + j];
        } else {
#pragma unroll
            for (int j = 0; j < 8; j++) dst[j] = acc[i][j];
        }
    }
}

// ---------------- zero fill (float4) ----------------
__global__ void zero_agg_kernel() {
    size_t i = (size_t)blockIdx.x * blockDim.x + threadIdx.x;
    if (i < (size_t)NN * HH / 4)
        ((float4*)g_agg)[i] = make_float4(0.f, 0.f, 0.f, 0.f);
}

// ---------------- edge: warp per edge, float4 lanes ----------------
__device__ __forceinline__ float sig_(float x) {
    return 1.0f / (1.0f + __expf(-x));
}

__global__ __launch_bounds__(256) void edge_kernel() {
    int gtid = blockIdx.x * blockDim.x + threadIdx.x;
    int e = gtid >> 5;
    if (e >= EE) return;
    int lane = gtid & 31;
    int r = g_rec[e], s = g_send[e];
    float4 a  = *(const float4*)(g_A + (size_t)r * HH + lane * 4);
    float4 b  = *(const float4*)(g_B + (size_t)s * HH + lane * 4);
    float4 sv = *(const float4*)(g_S + (size_t)s * HH + lane * 4);
    float* dst = g_agg + (size_t)r * HH + lane * 4;
    atomicAdd(dst + 0, sig_(a.x + b.x) * sv.x);
    atomicAdd(dst + 1, sig_(a.y + b.y) * sv.y);
    atomicAdd(dst + 2, sig_(a.z + b.z) * sv.z);
    atomicAdd(dst + 3, sig_(a.w + b.w) * sv.w);
}

// ---------------- node update: h += relu(R + agg) (float4) ----------------
__global__ void update_kernel() {
    size_t i = (size_t)blockIdx.x * blockDim.x + threadIdx.x;
    if (i >= (size_t)NN * HH / 4) return;
    float4 r = ((const float4*)g_R)[i];
    float4 g = ((const float4*)g_agg)[i];
    float4 h = ((float4*)g_h)[i];
    h.x += fmaxf(r.x + g.x, 0.f);
    h.y += fmaxf(r.y + g.y, 0.f);
    h.z += fmaxf(r.z + g.z, 0.f);
    h.w += fmaxf(r.w + g.w, 0.f);
    ((float4*)g_h)[i] = h;
}

// ---------------- pool: block per graph, thread per feature ----------------
__global__ __launch_bounds__(HH) void pool_kernel() {
    int g = blockIdx.x;
    int j = threadIdx.x;
    int n0 = g_start[g], n1 = g_start[g + 1];
    float s = 0.f;
    for (int n = n0; n < n1; n++) s += g_h[(size_t)n * HH + j];
    g_pool[g * HH + j] = s;
}

// ---------------- readout MLP: block per graph ----------------
__global__ __launch_bounds__(64) void mlp_kernel(const float* __restrict__ W1,
                                                 const float* __restrict__ b1,
                                                 const float* __restrict__ W2,
                                                 const float* __restrict__ b2,
                                                 float* __restrict__ out) {
    int g = blockIdx.x;
    int j = threadIdx.x;
    __shared__ float hp[HH];
    __shared__ float red[64];
    hp[j] = g_pool[g * HH + j];
    hp[64 + j] = g_pool[g * HH + 64 + j];
    __syncthreads();
    float acc = b1[j];
    for (int k = 0; k < HH; k++) acc += hp[k] * W1[k * 64 + j];
    red[j] = fmaxf(acc, 0.f) * W2[j];
    for (int off = 32; off > 0; off >>= 1) {
        __syncthreads();
        if (j < off) red[j] += red[j + off];
    }
    __syncthreads();
    if (j == 0) out[g] = red[0] + b2[0];
}

// ---------------- launch ----------------
extern "C" void kernel_launch(void* const* d_in, const int* in_sizes, int n_in,
                              void* d_out, int out_size)
{
    int used[64];
    for (int i = 0; i < 64; i++) used[i] = 0;
    auto find = [&](long long s1, long long s2) -> const void* {
        for (int i = 0; i < n_in; i++) {
            if (used[i]) continue;
            if ((long long)in_sizes[i] == s1 ||
                (s2 && (long long)in_sizes[i] == s2)) {
                used[i] = 1;
                return d_in[i];
            }
        }
        return d_in[0];
    };

    const float* h_in    = (const float*)find(6400000, 0);
    const void*  ei      = find(1200000, 2400000);
    const void*  ba      = find(50000, 100000);
    const float* Wg      = (const float*)find(131072, 0);
    const float* Ws      = (const float*)find(65536, 0);   // first 65536 (Ws before Wr)
    const float* Wr      = (const float*)find(65536, 0);
    const float* W_embed = (const float*)find(16384, 0);
    const float* W1      = (const float*)find(8192, 0);
    const float* bg      = (const float*)find(512, 0);     // bg, bs, br in order
    const float* bs      = (const float*)find(512, 0);
    const float* br      = (const float*)find(512, 0);
    const float* b_embed = (const float*)find(128, 0);
    const float* b1      = (const float*)find(64, 0);      // b1 before W2
    const float* W2      = (const float*)find(64, 0);
    const float* b2      = (const float*)find(1, 0);
    float* out = (float*)d_out;

    detect_kernel<<<1, 1>>>((const int*)ei, (const int*)ba);
    convert_edges<<<(EE + 255) / 256, 256>>>(ei);
    convert_batch<<<(NN + 255) / 256, 256>>>(ba);
    bounds_kernel<<<(NN + 255) / 256, 256>>>();

    const int gemmGrid = (NN + 63) / 64;   // 782

    // resolve device-global addresses for outputs (pure address query; capture-legal)
    float *pA, *pB, *pS, *pR, *pH;
    cudaGetSymbolAddress((void**)&pA, g_A);
    cudaGetSymbolAddress((void**)&pB, g_B);
    cudaGetSymbolAddress((void**)&pS, g_S);
    cudaGetSymbolAddress((void**)&pR, g_R);
    cudaGetSymbolAddress((void**)&pH, g_h);

    // embed: g_h = h_in @ W_embed + b_embed
    gemm128<<<gemmGrid, 256>>>(h_in, W_embed, b_embed, pH, NN);

    const size_t q4 = (size_t)NN * HH / 4;

    for (int l = 0; l < LL; l++) {
        const float* WgTop = Wg + (size_t)l * 2 * HH * HH;
        const float* WgBot = WgTop + (size_t)HH * HH;
        const float* Wsl   = Ws + (size_t)l * HH * HH;
        const float* Wrl   = Wr + (size_t)l * HH * HH;
        gemm128<<<gemmGrid, 256>>>(pH, WgTop, bg + l * HH, pA, NN);
        gemm128<<<gemmGrid, 256>>>(pH, WgBot, (const float*)nullptr, pB, NN);
        gemm128<<<gemmGrid, 256>>>(pH, Wsl,   bs + l * HH, pS, NN);
        gemm128<<<gemmGrid, 256>>>(pH, Wrl,   br + l * HH, pR, NN);
        zero_agg_kernel<<<(int)((q4 + 255) / 256), 256>>>();
        edge_kernel<<<(EE * 32 + 255) / 256, 256>>>();
        update_kernel<<<(int)((q4 + 255) / 256), 256>>>();
    }

    pool_kernel<<<GG, HH>>>();
    mlp_kernel<<<GG, 64>>>(W1, b1, W2, b2, out);
}

// round 12
// speedup vs baseline: 2.7804x; 1.0944x over previous
#include <cuda_runtime.h>
#include <cuda_bf16.h>
#include <math.h>

#define NN 50000
#define EE 600000
#define HH 128
#define GG 256
#define LL 4

// ---------------- scratch (static device allocations, legal) ----------------
__device__ float g_h[(size_t)NN * HH];
__device__ float g_A[(size_t)NN * HH];
__device__ float g_B[(size_t)NN * HH];
__device__ float g_S[(size_t)NN * HH];
__device__ float g_R[(size_t)NN * HH];
__device__ float g_agg[(size_t)NN * HH];
__device__ float g_pool[GG * HH];
__device__ int   g_send[EE];
__device__ int   g_rec[EE];
__device__ int   g_batch[NN];
__device__ int   g_start[GG + 1];
__device__ int   g_flag_e;
__device__ int   g_flag_b;

// ---------------- dtype detection (int64 vs int32) ----------------
__global__ void detect_kernel(const int* ei_words, const int* ba_words) {
    if (blockIdx.x != 0 || threadIdx.x != 0) return;
    int zeros = 0;
    for (int i = 0; i < 1024; i++) zeros += (ei_words[2 * i + 1] == 0);
    g_flag_e = (zeros > 512);
    int zb = 0;
    for (int i = 0; i < 1024; i++) {
        int w = NN / 2 + 2 * i + 1;
        zb += (ba_words[w] == 0);
    }
    g_flag_b = (zb > 512);
}

__global__ void convert_edges(const void* ei) {
    int i = blockIdx.x * blockDim.x + threadIdx.x;
    if (i >= EE) return;
    if (g_flag_e) {
        const long long* p = (const long long*)ei;
        g_send[i] = (int)p[i];
        g_rec[i]  = (int)p[EE + i];
    } else {
        const int* p = (const int*)ei;
        g_send[i] = p[i];
        g_rec[i]  = p[EE + i];
    }
}

__global__ void convert_batch(const void* ba) {
    int i = blockIdx.x * blockDim.x + threadIdx.x;
    if (i >= NN) return;
    if (g_flag_b) g_batch[i] = (int)((const long long*)ba)[i];
    else          g_batch[i] = ((const int*)ba)[i];
}

// ---------------- graph boundaries from sorted batch ----------------
__global__ void bounds_kernel() {
    int i = blockIdx.x * blockDim.x + threadIdx.x;
    if (i >= NN) return;
    int b = g_batch[i];
    if (i == 0) {
        for (int g = 0; g <= b; g++) g_start[g] = 0;
    } else {
        int pb = g_batch[i - 1];
        for (int g = pb + 1; g <= b; g++) g_start[g] = i;
    }
    if (i == NN - 1) {
        for (int g = b + 1; g <= GG; g++) g_start[g] = NN;
    }
}

// ---------------- tiled SGEMM: C[M,128] = A[M,128] @ W[128,128] (+bias) ----
// Block tile: 128 rows x 128 cols. 256 threads, each computes 8x8 outputs.
// Inner loop: 64 FMA vs 4x LDS.128 per thread per k -> FMA-issue bound.
__global__ __launch_bounds__(256) void gemm128(const float* __restrict__ A,
                                               const float* __restrict__ W,
                                               const float* __restrict__ bias,
                                               float* __restrict__ C, int M)
{
    __shared__ float As[8][128];   // [k][row], transposed for row-broadcast
    __shared__ float Bs[8][128];   // [k][col]
    const int t = threadIdx.x;
    const int rowBase = blockIdx.x * 128;
    const int ty = t >> 4;          // 0..15 -> rows ty*8 .. ty*8+7
    const int tx = t & 15;          // 0..15 -> cols tx*8 .. tx*8+7

    // A-tile load: 128 rows x 8 k = 1024 floats; thread loads float4 along k.
    const int aRow = t >> 1;            // 0..127
    const int aK4  = (t & 1) * 4;       // 0 or 4
    // W-tile load: 8 k-rows x 128 cols; thread loads float4 along cols.
    const int bRow  = t >> 5;           // 0..7
    const int bCol4 = (t & 31) * 4;     // 0..124

    float acc[8][8] = {};

    for (int kt = 0; kt < HH; kt += 8) {
        float4 av = make_float4(0.f, 0.f, 0.f, 0.f);
        int gm = rowBase + aRow;
        if (gm < M) av = *(const float4*)(A + (size_t)gm * HH + kt + aK4);
        As[aK4 + 0][aRow] = av.x;
        As[aK4 + 1][aRow] = av.y;
        As[aK4 + 2][aRow] = av.z;
        As[aK4 + 3][aRow] = av.w;
        float4 wv = *(const float4*)(W + (size_t)(kt + bRow) * HH + bCol4);
        *(float4*)&Bs[bRow][bCol4] = wv;
        __syncthreads();

#pragma unroll
        for (int k = 0; k < 8; k++) {
            float4 ra0 = *(const float4*)&As[k][ty * 8];
            float4 ra1 = *(const float4*)&As[k][ty * 8 + 4];
            float4 rb0 = *(const float4*)&Bs[k][tx * 8];
            float4 rb1 = *(const float4*)&Bs[k][tx * 8 + 4];
            float ra[8] = {ra0.x, ra0.y, ra0.z, ra0.w, ra1.x, ra1.y, ra1.z, ra1.w};
            float rb[8] = {rb0.x, rb0.y, rb0.z, rb0.w, rb1.x, rb1.y, rb1.z, rb1.w};
#pragma unroll
            for (int i = 0; i < 8; i++)
#pragma unroll
                for (int j = 0; j < 8; j++)
                    acc[i][j] += ra[i] * rb[j];
        }
        __syncthreads();
    }

#pragma unroll
    for (int i = 0; i < 8; i++) {
        int gm = rowBase + ty * 8 + i;
        if (gm >= M) continue;
        float* dst = C + (size_t)gm * HH + tx * 8;
        if (bias) {
            const float* bb = bias + tx * 8;
#pragma unroll
            for (int j = 0; j < 8; j++) dst[j] = acc[i][j] + bb[j];
        } else {
#pragma unroll
            for (int j = 0; j < 8; j++) dst[j] = acc[i][j];
        }
    }
}

// ---------------- zero fill (float4) ----------------
__global__ void zero_agg_kernel() {
    size_t i = (size_t)blockIdx.x * blockDim.x + threadIdx.x;
    if (i < (size_t)NN * HH / 4)
        ((float4*)g_agg)[i] = make_float4(0.f, 0.f, 0.f, 0.f);
}

// ---------------- edge: warp per edge, float4 lanes ----------------
__device__ __forceinline__ float sig_(float x) {
    return 1.0f / (1.0f + __expf(-x));
}

__global__ __launch_bounds__(256) void edge_kernel() {
    int gtid = blockIdx.x * blockDim.x + threadIdx.x;
    int e = gtid >> 5;
    if (e >= EE) return;
    int lane = gtid & 31;
    int r = g_rec[e], s = g_send[e];
    float4 a  = *(const float4*)(g_A + (size_t)r * HH + lane * 4);
    float4 b  = *(const float4*)(g_B + (size_t)s * HH + lane * 4);
    float4 sv = *(const float4*)(g_S + (size_t)s * HH + lane * 4);
    float* dst = g_agg + (size_t)r * HH + lane * 4;
    atomicAdd(dst + 0, sig_(a.x + b.x) * sv.x);
    atomicAdd(dst + 1, sig_(a.y + b.y) * sv.y);
    atomicAdd(dst + 2, sig_(a.z + b.z) * sv.z);
    atomicAdd(dst + 3, sig_(a.w + b.w) * sv.w);
}

// ---------------- node update: h += relu(R + agg); re-zero agg ----------------
__global__ void update_kernel() {
    size_t i = (size_t)blockIdx.x * blockDim.x + threadIdx.x;
    if (i >= (size_t)NN * HH / 4) return;
    float4 r = ((const float4*)g_R)[i];
    float4 g = ((const float4*)g_agg)[i];
    float4 h = ((float4*)g_h)[i];
    h.x += fmaxf(r.x + g.x, 0.f);
    h.y += fmaxf(r.y + g.y, 0.f);
    h.z += fmaxf(r.z + g.z, 0.f);
    h.w += fmaxf(r.w + g.w, 0.f);
    ((float4*)g_h)[i] = h;
    ((float4*)g_agg)[i] = make_float4(0.f, 0.f, 0.f, 0.f);   // ready for next layer
}

// ---------------- pool: block per graph, thread per feature ----------------
__global__ __launch_bounds__(HH) void pool_kernel() {
    int g = blockIdx.x;
    int j = threadIdx.x;
    int n0 = g_start[g], n1 = g_start[g + 1];
    float s = 0.f;
    for (int n = n0; n < n1; n++) s += g_h[(size_t)n * HH + j];
    g_pool[g * HH + j] = s;
}

// ---------------- readout MLP: block per graph ----------------
__global__ __launch_bounds__(64) void mlp_kernel(const float* __restrict__ W1,
                                                 const float* __restrict__ b1,
                                                 const float* __restrict__ W2,
                                                 const float* __restrict__ b2,
                                                 float* __restrict__ out) {
    int g = blockIdx.x;
    int j = threadIdx.x;
    __shared__ float hp[HH];
    __shared__ float red[64];
    hp[j] = g_pool[g * HH + j];
    hp[64 + j] = g_pool[g * HH + 64 + j];
    __syncthreads();
    float acc = b1[j];
    for (int k = 0; k < HH; k++) acc += hp[k] * W1[k * 64 + j];
    red[j] = fmaxf(acc, 0.f) * W2[j];
    for (int off = 32; off > 0; off >>= 1) {
        __syncthreads();
        if (j < off) red[j] += red[j + off];
    }
    __syncthreads();
    if (j == 0) out[g] = red[0] + b2[0];
}

// ---------------- launch ----------------
extern "C" void kernel_launch(void* const* d_in, const int* in_sizes, int n_in,
                              void* d_out, int out_size)
{
    int used[64];
    for (int i = 0; i < 64; i++) used[i] = 0;
    auto find = [&](long long s1, long long s2) -> const void* {
        for (int i = 0; i < n_in; i++) {
            if (used[i]) continue;
            if ((long long)in_sizes[i] == s1 ||
                (s2 && (long long)in_sizes[i] == s2)) {
                used[i] = 1;
                return d_in[i];
            }
        }
        return d_in[0];
    };

    const float* h_in    = (const float*)find(6400000, 0);
    const void*  ei      = find(1200000, 2400000);
    const void*  ba      = find(50000, 100000);
    const float* Wg      = (const float*)find(131072, 0);
    const float* Ws      = (const float*)find(65536, 0);   // first 65536 (Ws before Wr)
    const float* Wr      = (const float*)find(65536, 0);
    const float* W_embed = (const float*)find(16384, 0);
    const float* W1      = (const float*)find(8192, 0);
    const float* bg      = (const float*)find(512, 0);     // bg, bs, br in order
    const float* bs      = (const float*)find(512, 0);
    const float* br      = (const float*)find(512, 0);
    const float* b_embed = (const float*)find(128, 0);
    const float* b1      = (const float*)find(64, 0);      // b1 before W2
    const float* W2      = (const float*)find(64, 0);
    const float* b2      = (const float*)find(1, 0);
    float* out = (float*)d_out;

    detect_kernel<<<1, 1>>>((const int*)ei, (const int*)ba);
    convert_edges<<<(EE + 255) / 256, 256>>>(ei);
    convert_batch<<<(NN + 255) / 256, 256>>>(ba);
    bounds_kernel<<<(NN + 255) / 256, 256>>>();

    const int gemmGrid = (NN + 127) / 128;   // 391

    float *pA, *pB, *pS, *pR, *pH;
    cudaGetSymbolAddress((void**)&pA, g_A);
    cudaGetSymbolAddress((void**)&pB, g_B);
    cudaGetSymbolAddress((void**)&pS, g_S);
    cudaGetSymbolAddress((void**)&pR, g_R);
    cudaGetSymbolAddress((void**)&pH, g_h);

    // embed: g_h = h_in @ W_embed + b_embed
    gemm128<<<gemmGrid, 256>>>(h_in, W_embed, b_embed, pH, NN);

    const size_t q4 = (size_t)NN * HH / 4;
    zero_agg_kernel<<<(int)((q4 + 255) / 256), 256>>>();   // once; update re-zeroes

    for (int l = 0; l < LL; l++) {
        const float* WgTop = Wg + (size_t)l * 2 * HH * HH;
        const float* WgBot = WgTop + (size_t)HH * HH;
        const float* Wsl   = Ws + (size_t)l * HH * HH;
        const float* Wrl   = Wr + (size_t)l * HH * HH;
        gemm128<<<gemmGrid, 256>>>(pH, WgTop, bg + l * HH, pA, NN);
        gemm128<<<gemmGrid, 256>>>(pH, WgBot, (const float*)nullptr, pB, NN);
        gemm128<<<gemmGrid, 256>>>(pH, Wsl,   bs + l * HH, pS, NN);
        gemm128<<<gemmGrid, 256>>>(pH, Wrl,   br + l * HH, pR, NN);
        edge_kernel<<<(EE * 32 + 255) / 256, 256>>>();
        update_kernel<<<(int)((q4 + 255) / 256), 256>>>();
    }

    pool_kernel<<<GG, HH>>>();
    mlp_kernel<<<GG, 64>>>(W1, b1, W2, b2, out);
}

// round 13
// speedup vs baseline: 3.0423x; 1.0942x over previous
#include <cuda_runtime.h>
#include <cuda_bf16.h>
#include <math.h>

#define NN 50000
#define EE 600000
#define HH 128
#define GG 256
#define LL 4

// ---------------- scratch (static device allocations, legal) ----------------
__device__ float g_h[(size_t)NN * HH];
__device__ float g_A[(size_t)NN * HH];
__device__ float g_B[(size_t)NN * HH];
__device__ float g_S[(size_t)NN * HH];
__device__ float g_R[(size_t)NN * HH];
__device__ float g_agg[(size_t)NN * HH];
__device__ float g_pool[GG * HH];
__device__ int   g_send[EE];
__device__ int   g_rec[EE];
__device__ int   g_batch[NN];
__device__ int   g_start[GG + 1];
__device__ int   g_flag_e;
__device__ int   g_flag_b;

// ---------------- dtype detection (int64 vs int32) ----------------
__global__ void detect_kernel(const int* ei_words, const int* ba_words) {
    if (blockIdx.x != 0 || threadIdx.x != 0) return;
    int zeros = 0;
    for (int i = 0; i < 1024; i++) zeros += (ei_words[2 * i + 1] == 0);
    g_flag_e = (zeros > 512);
    int zb = 0;
    for (int i = 0; i < 1024; i++) {
        int w = NN / 2 + 2 * i + 1;
        zb += (ba_words[w] == 0);
    }
    g_flag_b = (zb > 512);
}

__global__ void convert_edges(const void* ei) {
    int i = blockIdx.x * blockDim.x + threadIdx.x;
    if (i >= EE) return;
    if (g_flag_e) {
        const long long* p = (const long long*)ei;
        g_send[i] = (int)p[i];
        g_rec[i]  = (int)p[EE + i];
    } else {
        const int* p = (const int*)ei;
        g_send[i] = p[i];
        g_rec[i]  = p[EE + i];
    }
}

__global__ void convert_batch(const void* ba) {
    int i = blockIdx.x * blockDim.x + threadIdx.x;
    if (i >= NN) return;
    if (g_flag_b) g_batch[i] = (int)((const long long*)ba)[i];
    else          g_batch[i] = ((const int*)ba)[i];
}

// ---------------- graph boundaries from sorted batch ----------------
__global__ void bounds_kernel() {
    int i = blockIdx.x * blockDim.x + threadIdx.x;
    if (i >= NN) return;
    int b = g_batch[i];
    if (i == 0) {
        for (int g = 0; g <= b; g++) g_start[g] = 0;
    } else {
        int pb = g_batch[i - 1];
        for (int g = pb + 1; g <= b; g++) g_start[g] = i;
    }
    if (i == NN - 1) {
        for (int g = b + 1; g <= GG; g++) g_start[g] = NN;
    }
}

// ---------------- tiled SGEMM: C[M,128] = A[M,128] @ W[128,128] (+bias) ----
// Block tile: 128x128, 256 threads, 8x8 outputs/thread.
// Double-buffered smem: prefetch tile k+1 into regs while computing tile k.
__global__ __launch_bounds__(256) void gemm128(const float* __restrict__ A,
                                               const float* __restrict__ W,
                                               const float* __restrict__ bias,
                                               float* __restrict__ C, int M)
{
    __shared__ float As[2][8][128];   // [buf][k][row]
    __shared__ float Bs[2][8][128];   // [buf][k][col]
    const int t = threadIdx.x;
    const int rowBase = blockIdx.x * 128;
    const int ty = t >> 4;          // 0..15 -> rows ty*8..ty*8+7
    const int tx = t & 15;          // 0..15 -> cols tx*8..tx*8+7

    const int aRow = t >> 1;            // 0..127
    const int aK4  = (t & 1) * 4;       // 0 or 4
    const int bRow  = t >> 5;           // 0..7
    const int bCol4 = (t & 31) * 4;     // 0..124

    const int gmLoad = rowBase + aRow;
    const bool aOk = (gmLoad < M);
    const float* aPtr = A + (size_t)gmLoad * HH + aK4;
    const float* wPtr = W + (size_t)bRow * HH + bCol4;

    float acc[8][8] = {};

    // stage tile 0
    float4 av = make_float4(0.f, 0.f, 0.f, 0.f);
    if (aOk) av = *(const float4*)(aPtr);
    float4 wv = *(const float4*)(wPtr);
    As[0][aK4 + 0][aRow] = av.x;
    As[0][aK4 + 1][aRow] = av.y;
    As[0][aK4 + 2][aRow] = av.z;
    As[0][aK4 + 3][aRow] = av.w;
    *(float4*)&Bs[0][bRow][bCol4] = wv;
    __syncthreads();

    int p = 0;
#pragma unroll
    for (int kt8 = 0; kt8 < 16; kt8++) {
        // prefetch next tile into registers (overlapped with compute)
        if (kt8 < 15) {
            int kn = (kt8 + 1) * 8;
            av = make_float4(0.f, 0.f, 0.f, 0.f);
            if (aOk) av = *(const float4*)(aPtr + kn);
            wv = *(const float4*)(wPtr + (size_t)kn * HH);
        }

#pragma unroll
        for (int k = 0; k < 8; k++) {
            float4 ra0 = *(const float4*)&As[p][k][ty * 8];
            float4 ra1 = *(const float4*)&As[p][k][ty * 8 + 4];
            float4 rb0 = *(const float4*)&Bs[p][k][tx * 8];
            float4 rb1 = *(const float4*)&Bs[p][k][tx * 8 + 4];
            float ra[8] = {ra0.x, ra0.y, ra0.z, ra0.w, ra1.x, ra1.y, ra1.z, ra1.w};
            float rb[8] = {rb0.x, rb0.y, rb0.z, rb0.w, rb1.x, rb1.y, rb1.z, rb1.w};
#pragma unroll
            for (int i = 0; i < 8; i++)
#pragma unroll
                for (int j = 0; j < 8; j++)
                    acc[i][j] += ra[i] * rb[j];
        }

        if (kt8 < 15) {
            __syncthreads();               // everyone done reading buf 1-p (last iter)
            int q = p ^ 1;
            As[q][aK4 + 0][aRow] = av.x;
            As[q][aK4 + 1][aRow] = av.y;
            As[q][aK4 + 2][aRow] = av.z;
            As[q][aK4 + 3][aRow] = av.w;
            *(float4*)&Bs[q][bRow][bCol4] = wv;
            __syncthreads();
            p = q;
        }
    }

#pragma unroll
    for (int i = 0; i < 8; i++) {
        int gm = rowBase + ty * 8 + i;
        if (gm >= M) continue;
        float* dst = C + (size_t)gm * HH + tx * 8;
        if (bias) {
            const float* bb = bias + tx * 8;
#pragma unroll
            for (int j = 0; j < 8; j++) dst[j] = acc[i][j] + bb[j];
        } else {
#pragma unroll
            for (int j = 0; j < 8; j++) dst[j] = acc[i][j];
        }
    }
}

// ---------------- zero fill (float4) ----------------
__global__ void zero_agg_kernel() {
    size_t i = (size_t)blockIdx.x * blockDim.x + threadIdx.x;
    if (i < (size_t)NN * HH / 4)
        ((float4*)g_agg)[i] = make_float4(0.f, 0.f, 0.f, 0.f);
}

// ---------------- edge: warp per edge, vectorized reduction ----------------
__device__ __forceinline__ float sig_(float x) {
    return 1.0f / (1.0f + __expf(-x));
}

__device__ __forceinline__ void red_add_f4(float* p, float x, float y, float z, float w) {
    asm volatile("red.global.add.v4.f32 [%0], {%1, %2, %3, %4};"
                 :: "l"(p), "f"(x), "f"(y), "f"(z), "f"(w) : "memory");
}

__global__ __launch_bounds__(256) void edge_kernel() {
    int gtid = blockIdx.x * blockDim.x + threadIdx.x;
    int e = gtid >> 5;
    if (e >= EE) return;
    int lane = gtid & 31;
    int r = g_rec[e], s = g_send[e];
    float4 a  = *(const float4*)(g_A + (size_t)r * HH + lane * 4);
    float4 b  = *(const float4*)(g_B + (size_t)s * HH + lane * 4);
    float4 sv = *(const float4*)(g_S + (size_t)s * HH + lane * 4);
    float* dst = g_agg + (size_t)r * HH + lane * 4;
    red_add_f4(dst,
               sig_(a.x + b.x) * sv.x,
               sig_(a.y + b.y) * sv.y,
               sig_(a.z + b.z) * sv.z,
               sig_(a.w + b.w) * sv.w);
}

// ---------------- node update: h += relu(R + agg); re-zero agg ----------------
__global__ void update_kernel() {
    size_t i = (size_t)blockIdx.x * blockDim.x + threadIdx.x;
    if (i >= (size_t)NN * HH / 4) return;
    float4 r = ((const float4*)g_R)[i];
    float4 g = ((const float4*)g_agg)[i];
    float4 h = ((float4*)g_h)[i];
    h.x += fmaxf(r.x + g.x, 0.f);
    h.y += fmaxf(r.y + g.y, 0.f);
    h.z += fmaxf(r.z + g.z, 0.f);
    h.w += fmaxf(r.w + g.w, 0.f);
    ((float4*)g_h)[i] = h;
    ((float4*)g_agg)[i] = make_float4(0.f, 0.f, 0.f, 0.f);   // ready for next layer
}

// ---------------- pool: block per graph, thread per feature ----------------
__global__ __launch_bounds__(HH) void pool_kernel() {
    int g = blockIdx.x;
    int j = threadIdx.x;
    int n0 = g_start[g], n1 = g_start[g + 1];
    float s = 0.f;
    for (int n = n0; n < n1; n++) s += g_h[(size_t)n * HH + j];
    g_pool[g * HH + j] = s;
}

// ---------------- readout MLP: block per graph ----------------
__global__ __launch_bounds__(64) void mlp_kernel(const float* __restrict__ W1,
                                                 const float* __restrict__ b1,
                                                 const float* __restrict__ W2,
                                                 const float* __restrict__ b2,
                                                 float* __restrict__ out) {
    int g = blockIdx.x;
    int j = threadIdx.x;
    __shared__ float hp[HH];
    __shared__ float red[64];
    hp[j] = g_pool[g * HH + j];
    hp[64 + j] = g_pool[g * HH + 64 + j];
    __syncthreads();
    float acc = b1[j];
    for (int k = 0; k < HH; k++) acc += hp[k] * W1[k * 64 + j];
    red[j] = fmaxf(acc, 0.f) * W2[j];
    for (int off = 32; off > 0; off >>= 1) {
        __syncthreads();
        if (j < off) red[j] += red[j + off];
    }
    __syncthreads();
    if (j == 0) out[g] = red[0] + b2[0];
}

// ---------------- launch ----------------
extern "C" void kernel_launch(void* const* d_in, const int* in_sizes, int n_in,
                              void* d_out, int out_size)
{
    int used[64];
    for (int i = 0; i < 64; i++) used[i] = 0;
    auto find = [&](long long s1, long long s2) -> const void* {
        for (int i = 0; i < n_in; i++) {
            if (used[i]) continue;
            if ((long long)in_sizes[i] == s1 ||
                (s2 && (long long)in_sizes[i] == s2)) {
                used[i] = 1;
                return d_in[i];
            }
        }
        return d_in[0];
    };

    const float* h_in    = (const float*)find(6400000, 0);
    const void*  ei      = find(1200000, 2400000);
    const void*  ba      = find(50000, 100000);
    const float* Wg      = (const float*)find(131072, 0);
    const float* Ws      = (const float*)find(65536, 0);   // first 65536 (Ws before Wr)
    const float* Wr      = (const float*)find(65536, 0);
    const float* W_embed = (const float*)find(16384, 0);
    const float* W1      = (const float*)find(8192, 0);
    const float* bg      = (const float*)find(512, 0);     // bg, bs, br in order
    const float* bs      = (const float*)find(512, 0);
    const float* br      = (const float*)find(512, 0);
    const float* b_embed = (const float*)find(128, 0);
    const float* b1      = (const float*)find(64, 0);      // b1 before W2
    const float* W2      = (const float*)find(64, 0);
    const float* b2      = (const float*)find(1, 0);
    float* out = (float*)d_out;

    detect_kernel<<<1, 1>>>((const int*)ei, (const int*)ba);
    convert_edges<<<(EE + 255) / 256, 256>>>(ei);
    convert_batch<<<(NN + 255) / 256, 256>>>(ba);
    bounds_kernel<<<(NN + 255) / 256, 256>>>();

    const int gemmGrid = (NN + 127) / 128;   // 391

    float *pA, *pB, *pS, *pR, *pH;
    cudaGetSymbolAddress((void**)&pA, g_A);
    cudaGetSymbolAddress((void**)&pB, g_B);
    cudaGetSymbolAddress((void**)&pS, g_S);
    cudaGetSymbolAddress((void**)&pR, g_R);
    cudaGetSymbolAddress((void**)&pH, g_h);

    // embed: g_h = h_in @ W_embed + b_embed
    gemm128<<<gemmGrid, 256>>>(h_in, W_embed, b_embed, pH, NN);

    const size_t q4 = (size_t)NN * HH / 4;
    zero_agg_kernel<<<(int)((q4 + 255) / 256), 256>>>();   // once; update re-zeroes

    for (int l = 0; l < LL; l++) {
        const float* WgTop = Wg + (size_t)l * 2 * HH * HH;
        const float* WgBot = WgTop + (size_t)HH * HH;
        const float* Wsl   = Ws + (size_t)l * HH * HH;
        const float* Wrl   = Wr + (size_t)l * HH * HH;
        gemm128<<<gemmGrid, 256>>>(pH, WgTop, bg + l * HH, pA, NN);
        gemm128<<<gemmGrid, 256>>>(pH, WgBot, (const float*)nullptr, pB, NN);
        gemm128<<<gemmGrid, 256>>>(pH, Wsl,   bs + l * HH, pS, NN);
        gemm128<<<gemmGrid, 256>>>(pH, Wrl,   br + l * HH, pR, NN);
        edge_kernel<<<(EE * 32 + 255) / 256, 256>>>();
        update_kernel<<<(int)((q4 + 255) / 256), 256>>>();
    }

    pool_kernel<<<GG, HH>>>();
    mlp_kernel<<<GG, 64>>>(W1, b1, W2, b2, out);
}

// round 16
// speedup vs baseline: 4.9995x; 1.6433x over previous
#include <cuda_runtime.h>
#include <cuda_bf16.h>
#include <mma.h>
#include <math.h>
#include <stdint.h>

using namespace nvcuda;

#define NN 50000
#define EE 600000
#define HH 128
#define GG 256
#define LL 4
#define NW 17          // 1 embed + 4 layers * 4 matrices

// ---------------- scratch ----------------
__device__ float g_h[(size_t)NN * HH];
__device__ float g_A[(size_t)NN * HH];
__device__ float g_B[(size_t)NN * HH];
__device__ float g_S[(size_t)NN * HH];
__device__ float g_R[(size_t)NN * HH];
__device__ float g_agg[(size_t)NN * HH];
__device__ float g_pool[GG * HH];
__device__ __nv_bfloat16 g_hh[(size_t)NN * HH];        // h hi (bf16)
__device__ __nv_bfloat16 g_hl[(size_t)NN * HH];        // h lo (bf16)
__device__ __nv_bfloat16 g_wth[(size_t)NW * HH * HH];  // W^T hi, [g][n][k]
__device__ __nv_bfloat16 g_wtl[(size_t)NW * HH * HH];  // W^T lo
__device__ int   g_send[EE];
__device__ int   g_rec[EE];
__device__ int   g_batch[NN];
__device__ int   g_start[GG + 1];
__device__ int   g_flag_e;
__device__ int   g_flag_b;

// ---------------- setup kernels ----------------
__global__ void detect_kernel(const int* ei_words, const int* ba_words) {
    if (blockIdx.x != 0 || threadIdx.x != 0) return;
    int zeros = 0;
    for (int i = 0; i < 1024; i++) zeros += (ei_words[2 * i + 1] == 0);
    g_flag_e = (zeros > 512);
    int zb = 0;
    for (int i = 0; i < 1024; i++) zb += (ba_words[NN / 2 + 2 * i + 1] == 0);
    g_flag_b = (zb > 512);
}

__global__ void convert_edges(const void* ei) {
    int i = blockIdx.x * blockDim.x + threadIdx.x;
    if (i >= EE) return;
    if (g_flag_e) {
        const long long* p = (const long long*)ei;
        g_send[i] = (int)p[i];
        g_rec[i]  = (int)p[EE + i];
    } else {
        const int* p = (const int*)ei;
        g_send[i] = p[i];
        g_rec[i]  = p[EE + i];
    }
}

__global__ void convert_batch(const void* ba) {
    int i = blockIdx.x * blockDim.x + threadIdx.x;
    if (i >= NN) return;
    if (g_flag_b) g_batch[i] = (int)((const long long*)ba)[i];
    else          g_batch[i] = ((const int*)ba)[i];
}

__global__ void bounds_kernel() {
    int i = blockIdx.x * blockDim.x + threadIdx.x;
    if (i >= NN) return;
    int b = g_batch[i];
    if (i == 0) { for (int g = 0; g <= b; g++) g_start[g] = 0; }
    else {
        int pb = g_batch[i - 1];
        for (int g = pb + 1; g <= b; g++) g_start[g] = i;
    }
    if (i == NN - 1) { for (int g = b + 1; g <= GG; g++) g_start[g] = NN; }
}

// transpose + split weights: dst[g][n][k] = W_g[k][n], hi/lo bf16
__global__ void prep_weights(const float* __restrict__ Wg, const float* __restrict__ Ws,
                             const float* __restrict__ Wr, const float* __restrict__ We) {
    int idx = blockIdx.x * blockDim.x + threadIdx.x;
    if (idx >= NW * HH * HH) return;
    int g = idx >> 14;
    int r = idx & 16383;
    int n = r >> 7;
    int k = r & 127;
    float v;
    if (g == 0) v = We[k * HH + n];
    else {
        int l = (g - 1) >> 2, w = (g - 1) & 3;
        if (w == 0)      v = Wg[((size_t)l * 256 + k) * HH + n];
        else if (w == 1) v = Wg[((size_t)l * 256 + 128 + k) * HH + n];
        else if (w == 2) v = Ws[((size_t)l * 128 + k) * HH + n];
        else             v = Wr[((size_t)l * 128 + k) * HH + n];
    }
    __nv_bfloat16 hi = __float2bfloat16(v);
    g_wth[idx] = hi;
    g_wtl[idx] = __float2bfloat16(v - __bfloat162float(hi));
}

__global__ void conv_hin(const float* __restrict__ x) {
    size_t i = (size_t)blockIdx.x * blockDim.x + threadIdx.x;
    if (i >= (size_t)NN * HH) return;
    float v = x[i];
    __nv_bfloat16 hi = __float2bfloat16(v);
    g_hh[i] = hi;
    g_hl[i] = __float2bfloat16(v - __bfloat162float(hi));
}

// ---------------- WMMA bf16-split GEMM ----------------
// C[M,128] = (Ah+Al) @ W + bias, computed as Ah@Wh + Ah@Wl + Al@Wh.
// Block: 128x128 tile, 256 threads = 8 warps (2 m x 4 n), warp tile 64x32.
// Full K=128 resident in smem; B is W^T[n][k] => wmma col_major matrix_b.
#define PA 136                              // padded pitch (halves)
#define TILE_B ((size_t)128 * PA * 2)       // 34816 bytes per tile
#define SMEM_DYN (4 * 128 * PA * 2)         // Ah|Al|Bh|Bl = 139264

__global__ __launch_bounds__(256) void gemm_wmma(
    const __nv_bfloat16* __restrict__ wth, const __nv_bfloat16* __restrict__ wtl,
    const float* __restrict__ bias, float* __restrict__ C,
    __nv_bfloat16* __restrict__ Chi, __nv_bfloat16* __restrict__ Clo, int M)
{
    extern __shared__ char smem[];
    __nv_bfloat16* Ah = (__nv_bfloat16*)(smem);
    __nv_bfloat16* Al = (__nv_bfloat16*)(smem + TILE_B);
    __nv_bfloat16* Bh = (__nv_bfloat16*)(smem + 2 * TILE_B);
    __nv_bfloat16* Bl = (__nv_bfloat16*)(smem + 3 * TILE_B);

    const int t = threadIdx.x;
    const int rowBase = blockIdx.x * 128;

    // ---- stage 4 tiles: 128 rows x 128 halves each (16 uint4 per row) ----
    {
        const __nv_bfloat16* srcs[4] = {g_hh, g_hl, wth, wtl};
        __nv_bfloat16* dsts[4] = {Ah, Al, Bh, Bl};
#pragma unroll
        for (int tile = 0; tile < 4; tile++) {
            const __nv_bfloat16* src = srcs[tile];
            __nv_bfloat16* dst = dsts[tile];
            bool isA = (tile < 2);
#pragma unroll
            for (int u = 0; u < 8; u++) {
                int idx = t + u * 256;          // 0..2047
                int row = idx >> 4;
                int c = idx & 15;               // uint4 within row
                uint4 v = make_uint4(0, 0, 0, 0);
                if (isA) {
                    int gm = rowBase + row;
                    if (gm < M) v = *(const uint4*)(src + (size_t)gm * HH + c * 8);
                } else {
                    v = *(const uint4*)(src + (size_t)row * HH + c * 8);
                }
                *(uint4*)(dst + row * PA + c * 8) = v;
            }
        }
    }
    __syncthreads();

    // ---- warp tiling: 2 m-warps x 4 n-warps ----
    const int wid = t >> 5;
    const int wm = wid & 1;         // 0..1 -> m0 = wm*64
    const int wn = wid >> 1;        // 0..3 -> n0 = wn*32
    const int m0 = wm * 64;
    const int n0 = wn * 32;

    wmma::fragment<wmma::accumulator, 16, 16, 16, float> acc[4][2];
#pragma unroll
    for (int i = 0; i < 4; i++)
#pragma unroll
        for (int j = 0; j < 2; j++)
            wmma::fill_fragment(acc[i][j], 0.0f);

#pragma unroll
    for (int k8 = 0; k8 < 8; k8++) {
        const int k0 = k8 * 16;
        wmma::fragment<wmma::matrix_a, 16, 16, 16, __nv_bfloat16, wmma::row_major> ah[4], al[4];
#pragma unroll
        for (int i = 0; i < 4; i++) {
            wmma::load_matrix_sync(ah[i], Ah + (m0 + i * 16) * PA + k0, PA);
            wmma::load_matrix_sync(al[i], Al + (m0 + i * 16) * PA + k0, PA);
        }
#pragma unroll
        for (int j = 0; j < 2; j++) {
            wmma::fragment<wmma::matrix_b, 16, 16, 16, __nv_bfloat16, wmma::col_major> bh, bl;
            wmma::load_matrix_sync(bh, Bh + (n0 + j * 16) * PA + k0, PA);
            wmma::load_matrix_sync(bl, Bl + (n0 + j * 16) * PA + k0, PA);
#pragma unroll
            for (int i = 0; i < 4; i++) {
                wmma::mma_sync(acc[i][j], ah[i], bh, acc[i][j]);
                wmma::mma_sync(acc[i][j], ah[i], bl, acc[i][j]);
                wmma::mma_sync(acc[i][j], al[i], bh, acc[i][j]);
            }
        }
    }

    // ---- epilogue: stage accumulators to smem (aliases A region), then write ----
    __syncthreads();                       // done reading Ah/Al
    float* Cs = (float*)smem;              // 128x128 f32 = 65536 <= 2*TILE_B
#pragma unroll
    for (int i = 0; i < 4; i++)
#pragma unroll
        for (int j = 0; j < 2; j++)
            wmma::store_matrix_sync(Cs + (m0 + i * 16) * 128 + (n0 + j * 16),
                                    acc[i][j], 128, wmma::mem_row_major);
    __syncthreads();

#pragma unroll
    for (int u = 0; u < 16; u++) {
        int idx = t + u * 256;             // 0..4095 float4 slots
        int row = idx >> 5;                // 32 float4 per row
        int c4 = idx & 31;
        int gm = rowBase + row;
        if (gm >= M) continue;
        float4 v = *(float4*)(Cs + row * 128 + c4 * 4);
        if (bias) {
            const float* bb = bias + c4 * 4;
            v.x += bb[0]; v.y += bb[1]; v.z += bb[2]; v.w += bb[3];
        }
        *(float4*)(C + (size_t)gm * HH + c4 * 4) = v;
        if (Chi) {
            size_t o = (size_t)gm * HH + c4 * 4;
            float vv[4] = {v.x, v.y, v.z, v.w};
#pragma unroll
            for (int q = 0; q < 4; q++) {
                __nv_bfloat16 hi = __float2bfloat16(vv[q]);
                Chi[o + q] = hi;
                Clo[o + q] = __float2bfloat16(vv[q] - __bfloat162float(hi));
            }
        }
    }
}

// ---------------- zero fill ----------------
__global__ void zero_agg_kernel() {
    size_t i = (size_t)blockIdx.x * blockDim.x + threadIdx.x;
    if (i < (size_t)NN * HH / 4)
        ((float4*)g_agg)[i] = make_float4(0.f, 0.f, 0.f, 0.f);
}

// ---------------- edge: warp per edge, red.v4 ----------------
__device__ __forceinline__ float sig_(float x) { return 1.0f / (1.0f + __expf(-x)); }
__device__ __forceinline__ void red_add_f4(float* p, float x, float y, float z, float w) {
    asm volatile("red.global.add.v4.f32 [%0], {%1, %2, %3, %4};"
                 :: "l"(p), "f"(x), "f"(y), "f"(z), "f"(w) : "memory");
}

__global__ __launch_bounds__(256) void edge_kernel() {
    int gtid = blockIdx.x * blockDim.x + threadIdx.x;
    int e = gtid >> 5;
    if (e >= EE) return;
    int lane = gtid & 31;
    int r = g_rec[e], s = g_send[e];
    float4 a  = *(const float4*)(g_A + (size_t)r * HH + lane * 4);
    float4 b  = *(const float4*)(g_B + (size_t)s * HH + lane * 4);
    float4 sv = *(const float4*)(g_S + (size_t)s * HH + lane * 4);
    red_add_f4(g_agg + (size_t)r * HH + lane * 4,
               sig_(a.x + b.x) * sv.x, sig_(a.y + b.y) * sv.y,
               sig_(a.z + b.z) * sv.z, sig_(a.w + b.w) * sv.w);
}

// ---------------- node update: h += relu(R+agg); refresh hi/lo; re-zero agg --
__global__ void update_kernel() {
    size_t i = (size_t)blockIdx.x * blockDim.x + threadIdx.x;
    if (i >= (size_t)NN * HH / 4) return;
    float4 r = ((const float4*)g_R)[i];
    float4 g = ((const float4*)g_agg)[i];
    float4 h = ((float4*)g_h)[i];
    h.x += fmaxf(r.x + g.x, 0.f);
    h.y += fmaxf(r.y + g.y, 0.f);
    h.z += fmaxf(r.z + g.z, 0.f);
    h.w += fmaxf(r.w + g.w, 0.f);
    ((float4*)g_h)[i] = h;
    ((float4*)g_agg)[i] = make_float4(0.f, 0.f, 0.f, 0.f);
    size_t b = i * 4;
    float hv[4] = {h.x, h.y, h.z, h.w};
#pragma unroll
    for (int j = 0; j < 4; j++) {
        __nv_bfloat16 hi = __float2bfloat16(hv[j]);
        g_hh[b + j] = hi;
        g_hl[b + j] = __float2bfloat16(hv[j] - __bfloat162float(hi));
    }
}

// ---------------- pool ----------------
__global__ __launch_bounds__(HH) void pool_kernel() {
    int g = blockIdx.x;
    int j = threadIdx.x;
    int n0 = g_start[g], n1 = g_start[g + 1];
    float s = 0.f;
    for (int n = n0; n < n1; n++) s += g_h[(size_t)n * HH + j];
    g_pool[g * HH + j] = s;
}

// ---------------- readout MLP ----------------
__global__ __launch_bounds__(64) void mlp_kernel(const float* __restrict__ W1,
                                                 const float* __restrict__ b1,
                                                 const float* __restrict__ W2,
                                                 const float* __restrict__ b2,
                                                 float* __restrict__ out) {
    int g = blockIdx.x;
    int j = threadIdx.x;
    __shared__ float hp[HH];
    __shared__ float red[64];
    hp[j] = g_pool[g * HH + j];
    hp[64 + j] = g_pool[g * HH + 64 + j];
    __syncthreads();
    float acc = b1[j];
    for (int k = 0; k < HH; k++) acc += hp[k] * W1[k * 64 + j];
    red[j] = fmaxf(acc, 0.f) * W2[j];
    for (int off = 32; off > 0; off >>= 1) {
        __syncthreads();
        if (j < off) red[j] += red[j + off];
    }
    __syncthreads();
    if (j == 0) out[g] = red[0] + b2[0];
}

// ---------------- launch ----------------
extern "C" void kernel_launch(void* const* d_in, const int* in_sizes, int n_in,
                              void* d_out, int out_size)
{
    int used[64];
    for (int i = 0; i < 64; i++) used[i] = 0;
    auto find = [&](long long s1, long long s2) -> const void* {
        for (int i = 0; i < n_in; i++) {
            if (used[i]) continue;
            if ((long long)in_sizes[i] == s1 ||
                (s2 && (long long)in_sizes[i] == s2)) {
                used[i] = 1;
                return d_in[i];
            }
        }
        return d_in[0];
    };

    const float* h_in    = (const float*)find(6400000, 0);
    const void*  ei      = find(1200000, 2400000);
    const void*  ba      = find(50000, 100000);
    const float* Wg      = (const float*)find(131072, 0);
    const float* Ws      = (const float*)find(65536, 0);
    const float* Wr      = (const float*)find(65536, 0);
    const float* W_embed = (const float*)find(16384, 0);
    const float* W1      = (const float*)find(8192, 0);
    const float* bg      = (const float*)find(512, 0);
    const float* bs      = (const float*)find(512, 0);
    const float* br      = (const float*)find(512, 0);
    const float* b_embed = (const float*)find(128, 0);
    const float* b1      = (const float*)find(64, 0);
    const float* W2      = (const float*)find(64, 0);
    const float* b2      = (const float*)find(1, 0);
    float* out = (float*)d_out;

    detect_kernel<<<1, 1>>>((const int*)ei, (const int*)ba);
    convert_edges<<<(EE + 255) / 256, 256>>>(ei);
    convert_batch<<<(NN + 255) / 256, 256>>>(ba);
    bounds_kernel<<<(NN + 255) / 256, 256>>>();
    prep_weights<<<(NW * HH * HH + 255) / 256, 256>>>(Wg, Ws, Wr, W_embed);
    conv_hin<<<(int)(((size_t)NN * HH + 255) / 256), 256>>>(h_in);

    float *pA, *pB, *pS, *pR, *pH;
    __nv_bfloat16 *pWth, *pWtl, *pHh, *pHl;
    cudaGetSymbolAddress((void**)&pA, g_A);
    cudaGetSymbolAddress((void**)&pB, g_B);
    cudaGetSymbolAddress((void**)&pS, g_S);
    cudaGetSymbolAddress((void**)&pR, g_R);
    cudaGetSymbolAddress((void**)&pH, g_h);
    cudaGetSymbolAddress((void**)&pWth, g_wth);
    cudaGetSymbolAddress((void**)&pWtl, g_wtl);
    cudaGetSymbolAddress((void**)&pHh, g_hh);
    cudaGetSymbolAddress((void**)&pHl, g_hl);

    cudaFuncSetAttribute(gemm_wmma, cudaFuncAttributeMaxDynamicSharedMemorySize, SMEM_DYN);

    const int grid = (NN + 127) / 128;   // 391
    const size_t wstep = (size_t)HH * HH;
    const size_t q4 = (size_t)NN * HH / 4;

    // embed: g_h = h_in @ W_embed + b_embed (also refresh hi/lo)
    gemm_wmma<<<grid, 256, SMEM_DYN>>>(pWth, pWtl, b_embed, pH, pHh, pHl, NN);
    zero_agg_kernel<<<(int)((q4 + 255) / 256), 256>>>();

    for (int l = 0; l < LL; l++) {
        int iA = 1 + l * 4, iB = iA + 1, iS = iA + 2, iR = iA + 3;
        gemm_wmma<<<grid, 256, SMEM_DYN>>>(pWth + iA * wstep, pWtl + iA * wstep,
                                           bg + l * HH, pA,
                                           (__nv_bfloat16*)nullptr, (__nv_bfloat16*)nullptr, NN);
        gemm_wmma<<<grid, 256, SMEM_DYN>>>(pWth + iB * wstep, pWtl + iB * wstep,
                                           (const float*)nullptr, pB,
                                           (__nv_bfloat16*)nullptr, (__nv_bfloat16*)nullptr, NN);
        gemm_wmma<<<grid, 256, SMEM_DYN>>>(pWth + iS * wstep, pWtl + iS * wstep,
                                           bs + l * HH, pS,
                                           (__nv_bfloat16*)nullptr, (__nv_bfloat16*)nullptr, NN);
        gemm_wmma<<<grid, 256, SMEM_DYN>>>(pWth + iR * wstep, pWtl + iR * wstep,
                                           br + l * HH, pR,
                                           (__nv_bfloat16*)nullptr, (__nv_bfloat16*)nullptr, NN);
        edge_kernel<<<(EE * 32 + 255) / 256, 256>>>();
        update_kernel<<<(int)((q4 + 255) / 256), 256>>>();
    }

    pool_kernel<<<GG, HH>>>();
    mlp_kernel<<<GG, 64>>>(W1, b1, W2, b2, out);
}